// round 2
// baseline (speedup 1.0000x reference)
#include <cuda_runtime.h>
#include <math.h>

// Problem constants
#define DM   512          // d_model = dim_k = dim_v
#define SEQ  2048
#define BB   2
#define NH   8
#define HD   64
#define MTOK (BB*SEQ)     // 4096 tokens
#define NG   (NH*BB)      // 16 attention groups (head-major view slices)

// Scratch (static device globals; allocation is forbidden)
__device__ float g_Qp[MTOK * DM];
__device__ float g_Kp[MTOK * DM];
__device__ float g_Vp[MTOK * DM];
__device__ float g_AO[MTOK * DM];
__device__ float g_S [(size_t)NG * SEQ * SEQ];   // 256 MB scores / probs

// ---------------------------------------------------------------------------
// NT GEMM: C[m,n] = sum_k A[m,k] * B[n,k] (+ bias[n])
// Tiles: BM=BN=128, BK=8, 256 threads, 8x8 microtile per thread.
// All dims assumed multiples of tile sizes (true for every call here).
// Batched via blockIdx.z with element strides sA/sB/sC.
// ---------------------------------------------------------------------------
__global__ __launch_bounds__(256) void gemm_nt(
    const float* __restrict__ A, const float* __restrict__ Bm,
    const float* __restrict__ bias, float* __restrict__ C,
    int M, int N, int K, int lda, int ldb, int ldc,
    long long sA, long long sB, long long sC)
{
    A  += (long long)blockIdx.z * sA;
    Bm += (long long)blockIdx.z * sB;
    C  += (long long)blockIdx.z * sC;

    __shared__ float As[8][128];
    __shared__ float Bs[8][128];

    const int tid = threadIdx.x;
    const int tr  = tid >> 4;       // 0..15 (m sub-block)
    const int tc  = tid & 15;       // 0..15 (n sub-block)
    const int m0  = blockIdx.y * 128;
    const int n0  = blockIdx.x * 128;

    const int lrow = tid >> 1;      // 0..127
    const int lseg = (tid & 1) * 4; // 0 or 4

    float acc[8][8];
    #pragma unroll
    for (int i = 0; i < 8; i++)
        #pragma unroll
        for (int j = 0; j < 8; j++) acc[i][j] = 0.f;

    for (int k0 = 0; k0 < K; k0 += 8) {
        float4 av = *(const float4*)&A [(long long)(m0 + lrow) * lda + k0 + lseg];
        float4 bv = *(const float4*)&Bm[(long long)(n0 + lrow) * ldb + k0 + lseg];
        __syncthreads();
        As[lseg + 0][lrow] = av.x; As[lseg + 1][lrow] = av.y;
        As[lseg + 2][lrow] = av.z; As[lseg + 3][lrow] = av.w;
        Bs[lseg + 0][lrow] = bv.x; Bs[lseg + 1][lrow] = bv.y;
        Bs[lseg + 2][lrow] = bv.z; Bs[lseg + 3][lrow] = bv.w;
        __syncthreads();
        #pragma unroll
        for (int kk = 0; kk < 8; kk++) {
            float4 a0 = *(const float4*)&As[kk][tr * 4];
            float4 a1 = *(const float4*)&As[kk][64 + tr * 4];
            float4 b0 = *(const float4*)&Bs[kk][tc * 4];
            float4 b1 = *(const float4*)&Bs[kk][64 + tc * 4];
            float a[8] = {a0.x,a0.y,a0.z,a0.w,a1.x,a1.y,a1.z,a1.w};
            float b[8] = {b0.x,b0.y,b0.z,b0.w,b1.x,b1.y,b1.z,b1.w};
            #pragma unroll
            for (int i = 0; i < 8; i++)
                #pragma unroll
                for (int j = 0; j < 8; j++)
                    acc[i][j] = fmaf(a[i], b[j], acc[i][j]);
        }
    }

    float bb[8] = {0,0,0,0,0,0,0,0};
    if (bias) {
        #pragma unroll
        for (int j = 0; j < 4; j++) {
            bb[j]     = bias[n0 + tc * 4 + j];
            bb[4 + j] = bias[n0 + 64 + tc * 4 + j];
        }
    }

    #pragma unroll
    for (int i = 0; i < 8; i++) {
        int mi = m0 + ((i < 4) ? (tr * 4 + i) : (64 + tr * 4 + i - 4));
        float4 o0 = make_float4(acc[i][0] + bb[0], acc[i][1] + bb[1],
                                acc[i][2] + bb[2], acc[i][3] + bb[3]);
        float4 o1 = make_float4(acc[i][4] + bb[4], acc[i][5] + bb[5],
                                acc[i][6] + bb[6], acc[i][7] + bb[7]);
        *(float4*)&C[(long long)mi * ldc + n0 + tc * 4]      = o0;
        *(float4*)&C[(long long)mi * ldc + n0 + 64 + tc * 4] = o1;
    }
}

// ---------------------------------------------------------------------------
// NN GEMM (for P @ V): C[m,n] = sum_k A[m,k] * B[k,n]
// BM=128, BN=64, BK=16, 256 threads, 8x4 microtile.
// ---------------------------------------------------------------------------
__global__ __launch_bounds__(256) void gemm_nn(
    const float* __restrict__ A, const float* __restrict__ Bm,
    float* __restrict__ C,
    int M, int N, int K, int lda, int ldb, int ldc,
    long long sA, long long sB, long long sC)
{
    A  += (long long)blockIdx.z * sA;
    Bm += (long long)blockIdx.z * sB;
    C  += (long long)blockIdx.z * sC;

    __shared__ float As[16][128];
    __shared__ float Bs[16][64];

    const int tid = threadIdx.x;
    const int tr  = tid >> 4;
    const int tc  = tid & 15;
    const int m0  = blockIdx.y * 128;
    const int n0  = blockIdx.x * 64;

    const int ar   = tid >> 2;        // 0..63
    const int aseg = (tid & 3) * 4;   // 0,4,8,12
    const int kr   = tid >> 4;        // 0..15
    const int ns   = (tid & 15) * 4;  // 0..60

    float acc[8][4];
    #pragma unroll
    for (int i = 0; i < 8; i++)
        #pragma unroll
        for (int j = 0; j < 4; j++) acc[i][j] = 0.f;

    for (int k0 = 0; k0 < K; k0 += 16) {
        float4 a0 = *(const float4*)&A [(long long)(m0 + ar)      * lda + k0 + aseg];
        float4 a1 = *(const float4*)&A [(long long)(m0 + 64 + ar) * lda + k0 + aseg];
        float4 bv = *(const float4*)&Bm[(long long)(k0 + kr)      * ldb + n0 + ns];
        __syncthreads();
        As[aseg + 0][ar] = a0.x; As[aseg + 1][ar] = a0.y;
        As[aseg + 2][ar] = a0.z; As[aseg + 3][ar] = a0.w;
        As[aseg + 0][64 + ar] = a1.x; As[aseg + 1][64 + ar] = a1.y;
        As[aseg + 2][64 + ar] = a1.z; As[aseg + 3][64 + ar] = a1.w;
        *(float4*)&Bs[kr][ns] = bv;
        __syncthreads();
        #pragma unroll
        for (int kk = 0; kk < 16; kk++) {
            float4 av0 = *(const float4*)&As[kk][tr * 4];
            float4 av1 = *(const float4*)&As[kk][64 + tr * 4];
            float4 bv0 = *(const float4*)&Bs[kk][tc * 4];
            float a[8] = {av0.x,av0.y,av0.z,av0.w,av1.x,av1.y,av1.z,av1.w};
            float b[4] = {bv0.x,bv0.y,bv0.z,bv0.w};
            #pragma unroll
            for (int i = 0; i < 8; i++)
                #pragma unroll
                for (int j = 0; j < 4; j++)
                    acc[i][j] = fmaf(a[i], b[j], acc[i][j]);
        }
    }

    #pragma unroll
    for (int i = 0; i < 8; i++) {
        int mi = m0 + ((i < 4) ? (tr * 4 + i) : (64 + tr * 4 + i - 4));
        float4 o = make_float4(acc[i][0], acc[i][1], acc[i][2], acc[i][3]);
        *(float4*)&C[(long long)mi * ldc + n0 + tc * 4] = o;
    }
}

// ---------------------------------------------------------------------------
// Fused mean-threshold masked softmax, in place, one block per score row.
// scores_scaled = raw * 1/sqrt(512); mask where <= row-mean; softmax.
// ---------------------------------------------------------------------------
__device__ __forceinline__ float warpSum(float v) {
    #pragma unroll
    for (int o = 16; o; o >>= 1) v += __shfl_xor_sync(0xffffffffu, v, o);
    return v;
}
__device__ __forceinline__ float warpMax(float v) {
    #pragma unroll
    for (int o = 16; o; o >>= 1) v = fmaxf(v, __shfl_xor_sync(0xffffffffu, v, o));
    return v;
}

__global__ __launch_bounds__(256) void softmax_mask_kernel(float* __restrict__ Sm)
{
    const float norm = 0.04419417382415922f;  // 1/sqrt(512)
    float* row = Sm + (size_t)blockIdx.x * SEQ;
    const int tid  = threadIdx.x;
    const int wid  = tid >> 5;
    const int lane = tid & 31;

    float4 v0 = ((const float4*)row)[tid];
    float4 v1 = ((const float4*)row)[tid + 256];
    float v[8] = {v0.x,v0.y,v0.z,v0.w,v1.x,v1.y,v1.z,v1.w};

    float lsum = 0.f, lmax = -3.4e38f;
    #pragma unroll
    for (int j = 0; j < 8; j++) {
        v[j] *= norm;
        lsum += v[j];
        lmax = fmaxf(lmax, v[j]);
    }

    __shared__ float ssum[8], smax[8], sden[8];
    float ws = warpSum(lsum), wm = warpMax(lmax);
    if (lane == 0) { ssum[wid] = ws; smax[wid] = wm; }
    __syncthreads();
    float tsum = 0.f, tmax = -3.4e38f;
    #pragma unroll
    for (int w = 0; w < 8; w++) { tsum += ssum[w]; tmax = fmaxf(tmax, smax[w]); }
    const float mean = tsum * (1.0f / (float)SEQ);

    float lden = 0.f;
    #pragma unroll
    for (int j = 0; j < 8; j++) {
        v[j] = (v[j] > mean) ? __expf(v[j] - tmax) : 0.f;
        lden += v[j];
    }
    float wd = warpSum(lden);
    if (lane == 0) sden[wid] = wd;
    __syncthreads();
    float tden = 0.f;
    #pragma unroll
    for (int w = 0; w < 8; w++) tden += sden[w];
    const float inv = 1.0f / tden;

    float4 o0 = make_float4(v[0]*inv, v[1]*inv, v[2]*inv, v[3]*inv);
    float4 o1 = make_float4(v[4]*inv, v[5]*inv, v[6]*inv, v[7]*inv);
    ((float4*)row)[tid]       = o0;
    ((float4*)row)[tid + 256] = o1;
}

// ---------------------------------------------------------------------------
// Launch
// ---------------------------------------------------------------------------
extern "C" void kernel_launch(void* const* d_in, const int* in_sizes, int n_in,
                              void* d_out, int out_size)
{
    const float* x   = (const float*)d_in[0];
    const float* y   = (const float*)d_in[1];
    const float* q_w = (const float*)d_in[2];
    const float* q_b = (const float*)d_in[3];
    const float* k_w = (const float*)d_in[4];
    const float* k_b = (const float*)d_in[5];
    const float* v_w = (const float*)d_in[6];
    const float* v_b = (const float*)d_in[7];
    const float* o_w = (const float*)d_in[8];
    const float* o_b = (const float*)d_in[9];
    float* out = (float*)d_out;

    float *Qp, *Kp, *Vp, *AO, *Sc;
    cudaGetSymbolAddress((void**)&Qp, g_Qp);
    cudaGetSymbolAddress((void**)&Kp, g_Kp);
    cudaGetSymbolAddress((void**)&Vp, g_Vp);
    cudaGetSymbolAddress((void**)&AO, g_AO);
    cudaGetSymbolAddress((void**)&Sc, g_S);

    dim3 blk(256);

    // QKV projections: [4096,512] @ [512,512]^T + bias
    gemm_nt<<<dim3(4, 32, 1), blk>>>(x, q_w, q_b, Qp, MTOK, DM, DM, DM, DM, DM, 0, 0, 0);
    gemm_nt<<<dim3(4, 32, 1), blk>>>(y, k_w, k_b, Kp, MTOK, DM, DM, DM, DM, DM, 0, 0, 0);
    gemm_nt<<<dim3(4, 32, 1), blk>>>(y, v_w, v_b, Vp, MTOK, DM, DM, DM, DM, DM, 0, 0, 0);

    // Batched scores: per group g, S_g = Q_g @ K_g^T  (M=N=2048, K=64)
    gemm_nt<<<dim3(16, 16, NG), blk>>>(Qp, Kp, nullptr, Sc,
                                       SEQ, SEQ, HD, HD, HD, SEQ,
                                       (long long)SEQ * HD, (long long)SEQ * HD,
                                       (long long)SEQ * SEQ);

    // Mean-threshold masked softmax (in place)
    softmax_mask_kernel<<<NG * SEQ, 256>>>(Sc);

    // AO_g = P_g @ V_g  (M=2048, N=64, K=2048)
    gemm_nn<<<dim3(1, 16, NG), blk>>>(Sc, Vp, AO,
                                      SEQ, HD, SEQ, SEQ, HD, HD,
                                      (long long)SEQ * SEQ, (long long)SEQ * HD,
                                      (long long)SEQ * HD);

    // Output projection: [4096,512] @ [512,512]^T + bias -> d_out
    gemm_nt<<<dim3(4, 32, 1), blk>>>(AO, o_w, o_b, out, MTOK, DM, DM, DM, DM, DM, 0, 0, 0);
}